// round 1
// baseline (speedup 1.0000x reference)
#include <cuda_runtime.h>

// YOLOv7 P3 head: B=16, A=3, NC=80 -> C=255 = 3*85, H=W=80, stride 8.
// Input  layout: [b, a, ch(85), h, w]   (ch-major, HW=6400 contiguous)
// Output layout: [b, a*h*w, 85]         (ch-last)
// Transform per channel:
//   ch0: (sigmoid(x) + grid_x) * 8
//   ch1: (sigmoid(x) + grid_y) * 8
//   ch2: exp(clip(x,-16,16)) * anchor_w[a]
//   ch3: exp(clip(x,-16,16)) * anchor_h[a]
//   ch4..84: sigmoid(x)

#define B_     16
#define A_     3
#define C_     85
#define W_     80
#define HW_    6400
#define TILE_  128      // spatial positions per block
#define PITCH_ 129      // smem pitch (odd -> conflict-free transpose read)
#define THREADS_ 256
#define QUADS_ (TILE_ / 4)         // 32 float4 per channel row
#define NVEC_  (C_ * QUADS_)       // 2720 float4 ops per phase

__device__ __forceinline__ float sigm(float x) {
    // 2 MUFU ops total (EX2 + RCP); rel err ~1e-6, well under 1e-3 gate.
    return __fdividef(1.0f, 1.0f + __expf(-x));
}

__global__ __launch_bounds__(THREADS_)
void yolo_head_kernel(const float* __restrict__ in,
                      const float* __restrict__ anchors,
                      float* __restrict__ out)
{
    __shared__ float s[C_ * PITCH_];   // 85*129*4 = 43,860 B

    const int tilesPerBA = HW_ / TILE_;          // 50
    const int bid  = blockIdx.x;
    const int ba   = bid / tilesPerBA;           // b*A + a  in [0,48)
    const int tile = bid - ba * tilesPerBA;
    const int pos0 = tile * TILE_;
    const int a    = ba % A_;

    const float aw = __ldg(&anchors[a * 2 + 0]);
    const float ah = __ldg(&anchors[a * 2 + 1]);

    const float* inBase = in + (size_t)ba * (C_ * HW_) + pos0;
    const int tid = threadIdx.x;

    // ---- Load + transform: coalesced LDG.128 along w, scatter to smem[ch][pos]
    for (int idx = tid; idx < NVEC_; idx += THREADS_) {
        const int ch = idx >> 5;        // idx / 32
        const int q  = idx & 31;        // quad within the 128-pos row
        float4 v = *reinterpret_cast<const float4*>(inBase + ch * HW_ + q * 4);
        float vv[4] = {v.x, v.y, v.z, v.w};

        if (ch >= 4) {
            #pragma unroll
            for (int j = 0; j < 4; j++) vv[j] = sigm(vv[j]);
        } else if (ch == 0) {
            const int g = pos0 + q * 4;
            #pragma unroll
            for (int j = 0; j < 4; j++) {
                const int w = (g + j) % W_;
                vv[j] = (sigm(vv[j]) + (float)w) * 8.0f;
            }
        } else if (ch == 1) {
            const int g = pos0 + q * 4;
            #pragma unroll
            for (int j = 0; j < 4; j++) {
                const int h = (g + j) / W_;
                vv[j] = (sigm(vv[j]) + (float)h) * 8.0f;
            }
        } else {  // ch == 2 or 3
            const float sc = (ch == 2) ? aw : ah;
            #pragma unroll
            for (int j = 0; j < 4; j++) {
                const float c = fminf(fmaxf(vv[j], -16.0f), 16.0f);
                vv[j] = __expf(c) * sc;
            }
        }

        const int p = q * 4;
        #pragma unroll
        for (int j = 0; j < 4; j++) s[ch * PITCH_ + p + j] = vv[j];
    }

    __syncthreads();

    // ---- Store: gather transposed scalars from smem, contiguous STG.128 out
    float* outBase = out + (size_t)(ba * HW_ + pos0) * C_;  // 16B-aligned (10880*4B tiles)
    for (int idx = tid; idx < NVEC_; idx += THREADS_) {
        const int i0 = idx * 4;
        float4 v;
        float* vp = &v.x;
        #pragma unroll
        for (int j = 0; j < 4; j++) {
            const int i   = i0 + j;
            const int pos = i / C_;          // mul-hi, no real div
            const int ch  = i - pos * C_;
            vp[j] = s[ch * PITCH_ + pos];
        }
        *reinterpret_cast<float4*>(outBase + i0) = v;
    }
}

extern "C" void kernel_launch(void* const* d_in, const int* in_sizes, int n_in,
                              void* d_out, int out_size) {
    const float* in      = (const float*)d_in[0];
    const float* anchors = (const float*)d_in[1];
    float* out           = (float*)d_out;

    const int blocks = B_ * A_ * (HW_ / TILE_);   // 2400
    yolo_head_kernel<<<blocks, THREADS_>>>(in, anchors, out);
}

// round 2
// speedup vs baseline: 1.1487x; 1.1487x over previous
#include <cuda_runtime.h>
#include <cstdint>

// YOLOv7 P3 head: B=16, A=3, C=85 per anchor, H=W=80, stride 8.
// Input:  [b, a, ch(85), h, w]  (ch-major, HW=6400 contiguous)
// Output: [b, a*h*w, 85]        (ch-last)
//
// Per block: 128 spatial positions of one (b,a). Transform in registers,
// scatter conflict-free into smem already in OUTPUT layout, then one
// cp.async.bulk (TMA) shared->global store. No LDS, no STG.

#define B_       16
#define A_       3
#define C_       85
#define W_       80
#define HW_      6400
#define TILE_    128
#define THREADS_ 256
#define OUT_FLOATS_ (TILE_ * C_)          // 10880
#define OUT_BYTES_  (OUT_FLOATS_ * 4)     // 43520 (16B-multiple)
#define NUNITS_  88                        // ceil(85/4)*4 units of (4ch x 8quads)

__device__ __forceinline__ float sigm(float x) {
    return __fdividef(1.0f, 1.0f + __expf(-x));   // 2 MUFU ops
}

__global__ __launch_bounds__(THREADS_)
void yolo_head_kernel(const float* __restrict__ in,
                      const float* __restrict__ anchors,
                      float* __restrict__ out)
{
    __shared__ alignas(128) float sbuf[OUT_FLOATS_];   // output-layout staging

    const int tilesPerBA = HW_ / TILE_;           // 50
    const int bid  = blockIdx.x;
    const int ba   = bid / tilesPerBA;            // b*A + a
    const int tile = bid - ba * tilesPerBA;
    const int pos0 = tile * TILE_;
    const int a    = ba % A_;

    const float aw = __ldg(&anchors[a * 2 + 0]);
    const float ah = __ldg(&anchors[a * 2 + 1]);

    const float* inBase = in + (size_t)ba * (C_ * HW_) + pos0;

    const int tid  = threadIdx.x;
    const int warp = tid >> 5;
    const int lane = tid & 31;
    const int c    = lane >> 3;      // 0..3  (channel within group)
    const int qq   = lane & 7;       // 0..7  (quad within sub-unit)

    // unit u = g*4 + s : group g of 4 channels, sub s selects quads [s*8, s*8+8)
    #pragma unroll 2
    for (int u = warp; u < NUNITS_; u += (THREADS_ / 32)) {
        const int g  = u >> 2;
        const int s  = u & 3;
        const int ch = g * 4 + c;
        if (ch < C_) {
            const int quad = s * 8 + qq;      // 0..31
            const int p    = quad * 4;        // local position base

            float4 v = *reinterpret_cast<const float4*>(inBase + ch * HW_ + p);
            float vv[4] = {v.x, v.y, v.z, v.w};

            if (ch >= 4) {
                #pragma unroll
                for (int j = 0; j < 4; j++) vv[j] = sigm(vv[j]);
            } else if (ch == 0) {
                const int gp = pos0 + p;
                #pragma unroll
                for (int j = 0; j < 4; j++) {
                    const int w = (gp + j) % W_;
                    vv[j] = (sigm(vv[j]) + (float)w) * 8.0f;
                }
            } else if (ch == 1) {
                const int gp = pos0 + p;
                #pragma unroll
                for (int j = 0; j < 4; j++) {
                    const int h = (gp + j) / W_;
                    vv[j] = (sigm(vv[j]) + (float)h) * 8.0f;
                }
            } else {  // ch == 2 or 3
                const float sc = (ch == 2) ? aw : ah;
                #pragma unroll
                for (int j = 0; j < 4; j++) {
                    const float cl = fminf(fmaxf(vv[j], -16.0f), 16.0f);
                    vv[j] = __expf(cl) * sc;
                }
            }

            // Conflict-free scatter: bank = (20*qq + c + K) mod 32 covers all 32.
            #pragma unroll
            for (int j = 0; j < 4; j++)
                sbuf[(p + j) * C_ + ch] = vv[j];
        }
    }

    __syncthreads();

    // One TMA bulk store of the whole tile (contiguous in output layout).
    if (tid == 0) {
        float* outBase = out + (size_t)(ba * HW_ + pos0) * C_;  // 16B-aligned
        uint32_t saddr;
        asm("{ .reg .u64 t; cvta.to.shared.u64 t, %1; cvt.u32.u64 %0, t; }"
            : "=r"(saddr) : "l"(sbuf));
        asm volatile("fence.proxy.async.shared::cta;" ::: "memory");
        asm volatile(
            "cp.async.bulk.global.shared::cta.bulk_group [%0], [%1], %2;"
            :: "l"(outBase), "r"(saddr), "r"((uint32_t)OUT_BYTES_) : "memory");
        asm volatile("cp.async.bulk.commit_group;" ::: "memory");
        asm volatile("cp.async.bulk.wait_group.read 0;" ::: "memory");
    }
}

extern "C" void kernel_launch(void* const* d_in, const int* in_sizes, int n_in,
                              void* d_out, int out_size) {
    const float* in      = (const float*)d_in[0];
    const float* anchors = (const float*)d_in[1];
    float* out           = (float*)d_out;

    const int blocks = B_ * A_ * (HW_ / TILE_);   // 2400
    yolo_head_kernel<<<blocks, THREADS_>>>(in, anchors, out);
}

// round 3
// speedup vs baseline: 1.3827x; 1.2037x over previous
#include <cuda_runtime.h>
#include <cstdint>

// YOLOv7 P3 head: B=16, A=3, C=85/anchor, H=W=80, stride 8.
// Input:  [b, a, ch(85), h, w]   Output: [b, a*h*w, 85]
//
// Block = 128 positions of one (b,a). Warp w owns units u = w + 8k (k=0..10),
// where u -> (g = u>>2 channel group, s = u&3 quad-range). s is constant per
// warp, so warps {0,1,4,5} fill output positions 0..63 and {2,3,6,7} fill
// 64..127: each half is TMA-stored as soon as its 4 warps finish.

#define B_       16
#define A_       3
#define C_       85
#define W_       80
#define HW_      6400
#define TILE_    128
#define THREADS_ 256
#define HALF_BYTES_ (64 * C_ * 4)   // 21760

__device__ __forceinline__ float sigm(float x) {
    float t;
    const float h = 0.5f * x;
    asm("tanh.approx.f32 %0, %1;" : "=f"(t) : "f"(h));   // 1 MUFU
    return fmaf(0.5f, t, 0.5f);
}

__global__ __launch_bounds__(THREADS_)
void yolo_head_kernel(const float* __restrict__ in,
                      const float* __restrict__ anchors,
                      float* __restrict__ out)
{
    __shared__ alignas(128) float sbuf[TILE_ * C_];   // output-layout staging

    const int bid  = blockIdx.x;
    const int ba   = bid / 50;            // b*A + a
    const int tile = bid - ba * 50;
    const int pos0 = tile * TILE_;
    const int a    = ba % A_;

    const float aw = __ldg(&anchors[a * 2 + 0]);
    const float ah = __ldg(&anchors[a * 2 + 1]);

    const int tid  = threadIdx.x;
    const int w    = tid >> 5;
    const int lane = tid & 31;
    const int c    = lane >> 3;          // channel-within-group 0..3
    const int qq   = lane & 7;           // quad-within-subrange 0..7
    const int s    = w & 3;              // quad range (position half: s<2 vs s>=2)
    const int g0   = w >> 2;             // starting channel group (0 or 1)
    const int p    = (s * 8 + qq) * 4;   // local position base 0..124
    const int ch0  = g0 * 4 + c;         // starting channel 0..7

    const float* tptr = in + (size_t)ba * (C_ * HW_) + pos0
                           + (size_t)ch0 * HW_ + p;

    float vv[4];

    // ---- batch 0: k = 0..5 (ch = ch0 + 8k <= 47, always valid) ----
    float4 r[6];
    #pragma unroll
    for (int k = 0; k < 6; k++)
        r[k] = *reinterpret_cast<const float4*>(tptr + (size_t)k * (8 * HW_));

    #pragma unroll
    for (int k = 0; k < 6; k++) {
        const int ch = ch0 + 8 * k;
        vv[0] = r[k].x; vv[1] = r[k].y; vv[2] = r[k].z; vv[3] = r[k].w;
        if (k == 0 && ch < 4) {          // only warps 0..3 hit this, once
            if (ch == 0) {
                const int gp = pos0 + p;
                #pragma unroll
                for (int j = 0; j < 4; j++)
                    vv[j] = (sigm(vv[j]) + (float)((gp + j) % W_)) * 8.0f;
            } else if (ch == 1) {
                const int gp = pos0 + p;
                #pragma unroll
                for (int j = 0; j < 4; j++)
                    vv[j] = (sigm(vv[j]) + (float)((gp + j) / W_)) * 8.0f;
            } else {
                const float sc = (ch == 2) ? aw : ah;
                #pragma unroll
                for (int j = 0; j < 4; j++) {
                    const float cl = fminf(fmaxf(vv[j], -16.0f), 16.0f);
                    vv[j] = __expf(cl) * sc;
                }
            }
        } else {
            #pragma unroll
            for (int j = 0; j < 4; j++) vv[j] = sigm(vv[j]);
        }
        // conflict-free: bank = (20*qq + c + const) mod 32 covers all 32
        #pragma unroll
        for (int j = 0; j < 4; j++) sbuf[(p + j) * C_ + ch] = vv[j];
    }

    // ---- batch 1: k = 6..10 (k==10 valid only when ch0 <= 4) ----
    const bool tailValid = (ch0 <= 4);
    float4 r2[5];
    #pragma unroll
    for (int k = 0; k < 5; k++) {
        if (k < 4 || tailValid)
            r2[k] = *reinterpret_cast<const float4*>(tptr + (size_t)(k + 6) * (8 * HW_));
    }
    #pragma unroll
    for (int k = 0; k < 5; k++) {
        if (k < 4 || tailValid) {
            const int ch = ch0 + 8 * (k + 6);    // >= 8: always generic path
            vv[0] = r2[k].x; vv[1] = r2[k].y; vv[2] = r2[k].z; vv[3] = r2[k].w;
            #pragma unroll
            for (int j = 0; j < 4; j++) vv[j] = sigm(vv[j]);
            #pragma unroll
            for (int j = 0; j < 4; j++) sbuf[(p + j) * C_ + ch] = vv[j];
        }
    }

    // ---- per-half named barrier, then TMA bulk store of that half ----
    if (s < 2) asm volatile("bar.sync 1, 128;" ::: "memory");   // warps 0,1,4,5
    else       asm volatile("bar.sync 2, 128;" ::: "memory");   // warps 2,3,6,7

    if (lane == 0 && (w == 0 || w == 2)) {
        const int half = (w == 2);
        float* outBase = out + ((size_t)(ba * HW_ + pos0) + half * 64) * C_;
        const float* src = sbuf + half * 64 * C_;
        uint32_t saddr;
        asm("{ .reg .u64 t; cvta.to.shared.u64 t, %1; cvt.u32.u64 %0, t; }"
            : "=r"(saddr) : "l"(src));
        asm volatile("fence.proxy.async.shared::cta;" ::: "memory");
        asm volatile("cp.async.bulk.global.shared::cta.bulk_group [%0], [%1], %2;"
                     :: "l"(outBase), "r"(saddr), "r"((uint32_t)HALF_BYTES_)
                     : "memory");
        asm volatile("cp.async.bulk.commit_group;" ::: "memory");
        asm volatile("cp.async.bulk.wait_group.read 0;" ::: "memory");
    }
}

extern "C" void kernel_launch(void* const* d_in, const int* in_sizes, int n_in,
                              void* d_out, int out_size) {
    const float* in      = (const float*)d_in[0];
    const float* anchors = (const float*)d_in[1];
    float* out           = (float*)d_out;

    const int blocks = B_ * A_ * (HW_ / TILE_);   // 2400
    yolo_head_kernel<<<blocks, THREADS_>>>(in, anchors, out);
}

// round 4
// speedup vs baseline: 1.5775x; 1.1408x over previous
#include <cuda_runtime.h>
#include <cstdint>

// YOLOv7 P3 head: B=16, A=3, C=85/anchor, H=W=80, stride 8.
// Input:  [b, a, ch(85), h, w]   Output: [b, a*h*w, 85]
//
// Block = 64 positions of one (b,a); smem 21.8KB -> 6 CTAs/SM (reg-capped).
// Warp w: s = w&1 (position half), g0 = w>>1 (channel group offset).
// Lane: c = lane>>3 (channel in group), qq = lane&7 (quad).
// Thread loads ch = ch0 + 16k (k=0..5, coalesced LDG.128), transforms,
// scatters conflict-free into output-layout smem, then per-half TMA store.

#define B_       16
#define A_       3
#define C_       85
#define W_       80
#define HW_      6400
#define TILE_    64
#define THREADS_ 256
#define HALF_BYTES_ (32 * C_ * 4)   // 10880

__device__ __forceinline__ float sigm(float x) {
    float t;
    const float h = 0.5f * x;
    asm("tanh.approx.f32 %0, %1;" : "=f"(t) : "f"(h));   // 1 MUFU
    return fmaf(0.5f, t, 0.5f);
}

__global__ __launch_bounds__(THREADS_, 6)
void yolo_head_kernel(const float* __restrict__ in,
                      const float* __restrict__ anchors,
                      float* __restrict__ out)
{
    __shared__ alignas(128) float sbuf[TILE_ * C_];   // 21760 B, output layout

    const int tilesPerBA = HW_ / TILE_;      // 100
    const int bid  = blockIdx.x;
    const int ba   = bid / tilesPerBA;       // b*A + a
    const int tile = bid - ba * tilesPerBA;
    const int pos0 = tile * TILE_;
    const int a    = ba % A_;

    const float aw = __ldg(&anchors[a * 2 + 0]);
    const float ah = __ldg(&anchors[a * 2 + 1]);

    const int tid  = threadIdx.x;
    const int w    = tid >> 5;
    const int lane = tid & 31;
    const int c    = lane >> 3;              // 0..3
    const int qq   = lane & 7;               // 0..7
    const int s    = w & 1;                  // position half
    const int g0   = w >> 1;                 // 0..3
    const int p    = (s * 8 + qq) * 4;       // local position base 0..60
    const int ch0  = g0 * 4 + c;             // 0..15

    const float* tptr = in + (size_t)ba * (C_ * HW_) + pos0
                           + (size_t)ch0 * HW_ + p;

    // ---- all loads upfront: ch = ch0 + 16k, k=0..5 (k=5 valid iff ch0<=4)
    const bool tailValid = (ch0 <= 4);
    float4 r[6];
    #pragma unroll
    for (int k = 0; k < 5; k++)
        r[k] = __ldcs(reinterpret_cast<const float4*>(tptr + (size_t)k * (16 * HW_)));
    if (tailValid)
        r[5] = __ldcs(reinterpret_cast<const float4*>(tptr + (size_t)5 * (16 * HW_)));

    float vv[4];
    #pragma unroll
    for (int k = 0; k < 6; k++) {
        if (k == 5 && !tailValid) break;
        const int ch = ch0 + 16 * k;
        vv[0] = r[k].x; vv[1] = r[k].y; vv[2] = r[k].z; vv[3] = r[k].w;

        if (k == 0 && ch < 4) {              // only warps 0,1 (g0==0), once
            if (ch == 0) {
                const int gp = pos0 + p;
                #pragma unroll
                for (int j = 0; j < 4; j++)
                    vv[j] = (sigm(vv[j]) + (float)((gp + j) % W_)) * 8.0f;
            } else if (ch == 1) {
                const int gp = pos0 + p;
                #pragma unroll
                for (int j = 0; j < 4; j++)
                    vv[j] = (sigm(vv[j]) + (float)((gp + j) / W_)) * 8.0f;
            } else {
                const float sc = (ch == 2) ? aw : ah;
                #pragma unroll
                for (int j = 0; j < 4; j++) {
                    const float cl = fminf(fmaxf(vv[j], -16.0f), 16.0f);
                    vv[j] = __expf(cl) * sc;
                }
            }
        } else {
            #pragma unroll
            for (int j = 0; j < 4; j++) vv[j] = sigm(vv[j]);
        }
        // bank = (20*qq + c + const) mod 32 -> all 32 distinct, conflict-free
        #pragma unroll
        for (int j = 0; j < 4; j++) sbuf[(p + j) * C_ + ch] = vv[j];
    }

    // ---- per-half named barrier (4 warps = 128 threads each), then TMA store
    if (s == 0) asm volatile("bar.sync 1, 128;" ::: "memory");  // warps 0,2,4,6
    else        asm volatile("bar.sync 2, 128;" ::: "memory");  // warps 1,3,5,7

    if (lane == 0 && w < 2) {                // warp 0 -> half 0, warp 1 -> half 1
        const int half = w;                  // == s for w<2
        float* outBase = out + ((size_t)(ba * HW_ + pos0) + half * 32) * C_;
        const float* src = sbuf + half * 32 * C_;
        uint32_t saddr;
        asm("{ .reg .u64 t; cvta.to.shared.u64 t, %1; cvt.u32.u64 %0, t; }"
            : "=r"(saddr) : "l"(src));
        asm volatile("fence.proxy.async.shared::cta;" ::: "memory");
        asm volatile("cp.async.bulk.global.shared::cta.bulk_group [%0], [%1], %2;"
                     :: "l"(outBase), "r"(saddr), "r"((uint32_t)HALF_BYTES_)
                     : "memory");
        asm volatile("cp.async.bulk.commit_group;" ::: "memory");
        asm volatile("cp.async.bulk.wait_group.read 0;" ::: "memory");
    }
}

extern "C" void kernel_launch(void* const* d_in, const int* in_sizes, int n_in,
                              void* d_out, int out_size) {
    const float* in      = (const float*)d_in[0];
    const float* anchors = (const float*)d_in[1];
    float* out           = (float*)d_out;

    const int blocks = B_ * A_ * (HW_ / TILE_);   // 4800
    yolo_head_kernel<<<blocks, THREADS_>>>(in, anchors, out);
}